// round 1
// baseline (speedup 1.0000x reference)
#include <cuda_runtime.h>

#define NHID 20
#define TPB  128
#define PPT  4   // points per thread (= 2 f32x2 pairs)

typedef unsigned long long u64;

static __device__ __forceinline__ u64 pack2f(float lo, float hi) {
    u64 r;
    unsigned a = __float_as_uint(lo), b = __float_as_uint(hi);
    asm("mov.b64 %0, {%1, %2};" : "=l"(r) : "r"(a), "r"(b));
    return r;
}
static __device__ __forceinline__ void unpack2f(u64 v, float& lo, float& hi) {
    unsigned a, b;
    asm("mov.b64 {%0, %1}, %2;" : "=r"(a), "=r"(b) : "l"(v));
    lo = __uint_as_float(a);
    hi = __uint_as_float(b);
}
// Packed dual-fp32 FMA (sm_103a): d = a*b + c on two lanes at once.
static __device__ __forceinline__ u64 fma2(u64 a, u64 b, u64 c) {
    u64 d;
    asm("fma.rn.f32x2 %0, %1, %2, %3;" : "=l"(d) : "l"(a), "l"(b), "l"(c));
    return d;
}

static __device__ __forceinline__ float silu1(float x) {
    float e = __expf(-x);               // FMUL-imm + MUFU.EX2
    return __fdividef(x, 1.0f + e);     // FADD + MUFU.RCP + FMUL
}
static __device__ __forceinline__ u64 silu2(u64 x2) {
    float a, b;
    unpack2f(x2, a, b);
    return pack2f(silu1(a), silu1(b));
}

__global__ void __launch_bounds__(TPB)
SpringEquationNN_kernel(
    const float* __restrict__ t,
    const float* __restrict__ W0, const float* __restrict__ b0,
    const float* __restrict__ W1, const float* __restrict__ b1,
    const float* __restrict__ W2, const float* __restrict__ b2,
    const float* __restrict__ W3, const float* __restrict__ b3,
    const float* __restrict__ W4, const float* __restrict__ b4,
    const float* __restrict__ W5, const float* __restrict__ b5,
    const float* __restrict__ W6, const float* __restrict__ b6,
    const float* __restrict__ W7, const float* __restrict__ b7,
    float* __restrict__ out, int n)
{
    // Weights duplicated as {w,w} 64-bit pairs: LDS.64 broadcast feeds FMA2 directly.
    __shared__ u64 sW0[NHID], sB0[NHID], sW7[NHID];
    __shared__ u64 sW[6 * NHID * NHID];
    __shared__ u64 sB[6 * NHID];
    __shared__ float sb7;

    const int tid = threadIdx.x;

    for (int i = tid; i < NHID; i += TPB) {
        sW0[i] = pack2f(W0[i], W0[i]);
        sB0[i] = pack2f(b0[i], b0[i]);
        sW7[i] = pack2f(W7[i], W7[i]);
    }
    for (int i = tid; i < 6 * NHID * NHID; i += TPB) {
        int l = i / (NHID * NHID);
        int r = i - l * (NHID * NHID);
        float w;
        switch (l) {
            case 0: w = W1[r]; break;
            case 1: w = W2[r]; break;
            case 2: w = W3[r]; break;
            case 3: w = W4[r]; break;
            case 4: w = W5[r]; break;
            default: w = W6[r]; break;
        }
        sW[i] = pack2f(w, w);
    }
    for (int i = tid; i < 6 * NHID; i += TPB) {
        int l = i / NHID;
        int r = i - l * NHID;
        float w;
        switch (l) {
            case 0: w = b1[r]; break;
            case 1: w = b2[r]; break;
            case 2: w = b3[r]; break;
            case 3: w = b4[r]; break;
            case 4: w = b5[r]; break;
            default: w = b6[r]; break;
        }
        sB[i] = pack2f(w, w);
    }
    if (tid == 0) sb7 = b7[0];
    __syncthreads();

    const int base = (blockIdx.x * TPB + tid) * PPT;
    if (base >= n) return;

    // Bounds-guarded element IO keeps one compute path for any n.
    float tv[PPT];
    #pragma unroll
    for (int p = 0; p < PPT; p++)
        tv[p] = (base + p < n) ? t[base + p] : 0.0f;

    u64 h[2][NHID], hn[2][NHID];
    const u64 t20 = pack2f(tv[0], tv[1]);
    const u64 t21 = pack2f(tv[2], tv[3]);

    // Layer 0: 1 -> 20
    #pragma unroll
    for (int j = 0; j < NHID; j++) {
        u64 w = sW0[j], bb = sB0[j];
        h[0][j] = silu2(fma2(t20, w, bb));
        h[1][j] = silu2(fma2(t21, w, bb));
    }

    // Hidden layers 1..6: 20 -> 20 (rolled layer loop, unrolled 20x20 body)
    for (int l = 0; l < 6; l++) {
        const u64* wl = &sW[l * NHID * NHID];
        const u64* bl = &sB[l * NHID];
        #pragma unroll
        for (int j = 0; j < NHID; j++) {
            u64 a0 = bl[j];
            u64 a1 = a0;
            #pragma unroll
            for (int k = 0; k < NHID; k++) {
                u64 w = wl[j * NHID + k];
                a0 = fma2(h[0][k], w, a0);
                a1 = fma2(h[1][k], w, a1);
            }
            hn[0][j] = silu2(a0);
            hn[1][j] = silu2(a1);
        }
        #pragma unroll
        for (int j = 0; j < NHID; j++) {
            h[0][j] = hn[0][j];
            h[1][j] = hn[1][j];
        }
    }

    // Output layer: 20 -> 1
    u64 a0 = pack2f(sb7, sb7);
    u64 a1 = a0;
    #pragma unroll
    for (int k = 0; k < NHID; k++) {
        u64 w = sW7[k];
        a0 = fma2(h[0][k], w, a0);
        a1 = fma2(h[1][k], w, a1);
    }

    float o[PPT];
    unpack2f(a0, o[0], o[1]);
    unpack2f(a1, o[2], o[3]);
    #pragma unroll
    for (int p = 0; p < PPT; p++)
        if (base + p < n) out[base + p] = o[p];
}

extern "C" void kernel_launch(void* const* d_in, const int* in_sizes, int n_in,
                              void* d_out, int out_size)
{
    const float* t  = (const float*)d_in[0];
    const float* W0 = (const float*)d_in[1];
    const float* b0 = (const float*)d_in[2];
    const float* W1 = (const float*)d_in[3];
    const float* b1 = (const float*)d_in[4];
    const float* W2 = (const float*)d_in[5];
    const float* b2 = (const float*)d_in[6];
    const float* W3 = (const float*)d_in[7];
    const float* b3 = (const float*)d_in[8];
    const float* W4 = (const float*)d_in[9];
    const float* b4 = (const float*)d_in[10];
    const float* W5 = (const float*)d_in[11];
    const float* b5 = (const float*)d_in[12];
    const float* W6 = (const float*)d_in[13];
    const float* b6 = (const float*)d_in[14];
    const float* W7 = (const float*)d_in[15];
    const float* b7 = (const float*)d_in[16];

    const int n = in_sizes[0];  // N points (t is [N,1])
    float* out = (float*)d_out;

    const int pts_per_block = TPB * PPT;
    const int grid = (n + pts_per_block - 1) / pts_per_block;

    SpringEquationNN_kernel<<<grid, TPB>>>(
        t, W0, b0, W1, b1, W2, b2, W3, b3,
        W4, b4, W5, b5, W6, b6, W7, b7, out, n);
}